// round 14
// baseline (speedup 1.0000x reference)
#include <cuda_runtime.h>
#include <math.h>

#define T_LEN    8192
#define NDELAY   360
#define NTHREADS 1024
#define FULLMASK 0xffffffffu

// smem float layout: [FPX zeros | X 8192 | 1024 tail] [FPB zeros | B 8192 | 1024 tail]
#define FPX 424                   // >= L1+1 max (421); also serves as Y front pad (K=1)
#define FPB 520                   // >= 2*L1+2 max on K=2 path; Y front pad (K=2)
#define OX  0
#define OB  (OX + FPX + T_LEN + 1024)
#define SMEM_FLOATS (OB + FPB + T_LEN + 1024)

// ---------------------------------------------------------------------------
// y_t = x_t - a1*y_{t-L1} - a2*y_{t-L2}; exactly two taps (straight-through
// one-hot exactly hard in fp32). L2 = L1+1 unless m==359 (fallback kept).
// 1/(1+s) = (1-s)/(1-s^2) = (1-s)(1+s^2)/(1-s^4).
// K=2 when L1<=256 (serial width W=4L1<=1024), else K=1 (W=2L1<=840).
// Serial remainder taps sit at CONSECUTIVE lags W..W+NT-1: thread p <-> slot
// p; tap0 = own prev-round register, tap k = shfl_up(k) (boundary lanes read
// the Y smem image from >= 1 round earlier; zero front pad covers t < 0).
// THIS ROUND: serial rounds dual-store (STS for later boundary reads + STG
// straight to out) and Y reuses the dead input buffer -> the entire final
// writeback pass, its barrier, and the third buffer are deleted. Stray slots
// (p >= W or t >= T_LEN) are either overwritten by the next round before any
// valid read (barrier-ordered) or store-suppressed at the T_LEN edge.
// ---------------------------------------------------------------------------

__device__ __forceinline__ float tanh_fast(float x) {
    x = fminf(fmaxf(x, -15.0f), 15.0f);
    float e = __expf(2.0f * x);
    return (e - 1.0f) * __frcp_rn(e + 1.0f);
}

// Cw: center input (previous pass output, tail-padded readable)
// Y:  serial image (reuses a dead buffer; front pad >= NT-1 zeros)
template <int NT>
__device__ __forceinline__ void serial_run(const float* __restrict__ Cw,
                                           float* __restrict__ Y,
                                           float* __restrict__ yr,
                                           const float* c, int W) {
    const int p    = threadIdx.x;
    const int lane = p & 31;

    // round 0: y = w on [0, W). Strays (p >= W) write slots the next round
    // overwrites (smem and gmem) before any valid read; barrier orders both.
    float yp = Cw[p];
    Y[p]  = yp;
    yr[p] = yp;
    __syncthreads();

    int s0 = W;
    while (s0 < T_LEN) {
        const int t = s0 + p;
        float cx = Cw[t];
        float u[NT - 1];
#pragma unroll
        for (int k = 1; k < NT; k++) {
            u[k - 1] = __shfl_up_sync(FULLMASK, yp, k);
            if (lane < k) u[k - 1] = Y[s0 - W + p - k];   // predicated LDS
        }
        float acc = fmaf(c[0], yp, cx);
#pragma unroll
        for (int k = 1; k < NT; k++) acc = fmaf(c[k], u[k - 1], acc);
        Y[t] = acc;
        if (t < T_LEN) yr[t] = acc;      // single-compare predicate
        __syncthreads();
        yp = acc;
        s0 += W;
    }
}

__global__ void __launch_bounds__(NTHREADS, 1)
ks_fused_kernel(const float* __restrict__ x,
                const float* __restrict__ gumbel,
                const float* __restrict__ delayp,
                const float* __restrict__ fb,
                const float* __restrict__ rc,
                float* __restrict__ out) {
    extern __shared__ float sm[];
    float* Xd = sm + OX + FPX;
    float* Bd = sm + OB + FPB;

    __shared__ float s_rv[32];
    __shared__ int   s_ri[32];
    __shared__ int   s_m;

    const int tid  = threadIdx.x;
    const int row  = blockIdx.x;
    const int lane = tid & 31;
    const int wid  = tid >> 5;
    const float* xr = x + (size_t)row * T_LEN;
    float*       yr = out + (size_t)row * T_LEN;

    // --- stage x (coalesced float4; LDG latency hidden under setup) ---
    {
        const float4* x4 = (const float4*)xr;
        float4* s4 = (float4*)Xd;
        s4[tid]            = x4[tid];
        s4[tid + NTHREADS] = x4[tid + NTHREADS];
    }

    // --- zero the front pads ---
    if (tid < FPX) sm[OX + tid] = 0.0f;
    if (tid < FPB) sm[OB + tid] = 0.0f;

    // --- argmax over 360 logits (first-index tie-break) ---
    float lv = -INFINITY;
    int   li = tid;
    if (tid < NDELAY) lv = delayp[tid] + gumbel[tid];
#pragma unroll
    for (int off = 16; off > 0; off >>= 1) {
        float ov = __shfl_down_sync(FULLMASK, lv, off);
        int   oi = __shfl_down_sync(FULLMASK, li, off);
        if (ov > lv || (ov == lv && oi < li)) { lv = ov; li = oi; }
    }
    if (lane == 0) { s_rv[wid] = lv; s_ri[wid] = li; }

    // --- scalar coefficients (redundant per thread, deterministic) ---
    float k1 = tanh_fast(tanh_fast(rc[0]));
    float k2 = tanh_fast(tanh_fast(rc[1]));
    float a1 = k1 * (1.0f - k2);
    float a2 = fminf(fmaxf(k2, -0.999f), 0.999f);
    float bound = 0.999f - fabsf(a2);
    a1 = fminf(fmaxf(a1, -bound), bound);
    float sg = __frcp_rn(1.0f + __expf(-fb[0]));
    float g  = __powf(sg, 0.45f);
    a1 *= g;
    a2 *= g;

    __syncthreads();
    if (tid < 32) {
        lv = s_rv[lane];
        li = s_ri[lane];
#pragma unroll
        for (int off = 16; off > 0; off >>= 1) {
            float ov = __shfl_down_sync(FULLMASK, lv, off);
            int   oi = __shfl_down_sync(FULLMASK, li, off);
            if (ov > lv || (ov == lv && oi < li)) { lv = ov; li = oi; }
        }
        if (lane == 0) s_m = li;
    }
    __syncthreads();   // staging + pads + argmax complete

    const int m  = s_m;
    const int L1 = 61 + m;
    const int L2 = 61 + ((m + 1) % NDELAY);

    if (L2 != L1 + 1) {
        // --- fallback (m == 359 only): in-place barrier rounds, width C ---
        const int C = (L1 < L2) ? L1 : L2;
        for (int t = tid; t < C; t += NTHREADS) yr[t] = Xd[t];
        for (int s0 = C; s0 < T_LEN; s0 += C) {
            __syncthreads();
            const int t = s0 + tid;
            if (tid < C && t < T_LEN) {
                float y = Xd[t] - a1 * Xd[t - L1] - a2 * Xd[t - L2];
                Xd[t] = y;
                yr[t] = y;
            }
        }
        return;
    }

    const float a1_2 = a1 * a1, a2_2 = a2 * a2;

    // --- pass 1: B = (1 - s) X, register carry (lags L1, L1+1) ---
    float rc8[8];
#pragma unroll
    for (int i = 0; i < 8; i++) {
        const int t = i * NTHREADS + tid;
        float w = fmaf(-a1, Xd[t - L1], Xd[t]);
        w = fmaf(-a2, Xd[t - L1 - 1], w);
        Bd[t] = w;
        rc8[i] = w;
    }
    __syncthreads();

    if (L1 <= 256) {
        // --- K=2: pass 2: X = (1 + s^2) B  (x dead; X becomes w2) ---
        const float q0 = a1_2, q1 = 2.0f * a1 * a2, q2 = a2_2;
        const int gl = 2 * L1;
#pragma unroll
        for (int i = 0; i < 8; i++) {
            const int t = i * NTHREADS + tid;
            float w = fmaf(q0, Bd[t - gl], rc8[i]);
            w = fmaf(q1, Bd[t - gl - 1], w);
            w = fmaf(q2, Bd[t - gl - 2], w);
            Xd[t] = w;
        }
        __syncthreads();
        // serial: y = w2 + s^4 y, taps at 4L1..4L1+4; Y reuses B (dead)
        const float c[5] = { a1_2 * a1_2, 4.0f * a1_2 * a1 * a2,
                             6.0f * a1_2 * a2_2, 4.0f * a1 * a2_2 * a2,
                             a2_2 * a2_2 };
        serial_run<5>(Xd, Bd, yr, c, 4 * L1);
    } else {
        // --- K=1: serial: y = w + s^2 y, taps at 2L1..2L1+2; Y reuses X ---
        const float c[3] = { a1_2, 2.0f * a1 * a2, a2_2 };
        serial_run<3>(Bd, Xd, yr, c, 2 * L1);
    }
}

// ---------------------------------------------------------------------------
// inputs: excitation[128*8192] f32, gumbel[360], delay_param[360],
//         feedback_gain[1], reflection_coeffs[2]; output f32 [128*8192]
// ---------------------------------------------------------------------------
extern "C" void kernel_launch(void* const* d_in, const int* in_sizes, int n_in,
                              void* d_out, int out_size) {
    const float* x      = (const float*)d_in[0];
    const float* gumbel = (const float*)d_in[1];
    const float* delayp = (const float*)d_in[2];
    const float* fb     = (const float*)d_in[3];
    const float* rc     = (const float*)d_in[4];
    float* out = (float*)d_out;

    const int rows = in_sizes[0] / T_LEN;
    const int smem_bytes = SMEM_FLOATS * sizeof(float);

    cudaFuncSetAttribute(ks_fused_kernel,
                         cudaFuncAttributeMaxDynamicSharedMemorySize, smem_bytes);
    ks_fused_kernel<<<rows, NTHREADS, smem_bytes>>>(x, gumbel, delayp, fb, rc, out);
}

// round 15
// speedup vs baseline: 1.0209x; 1.0209x over previous
#include <cuda_runtime.h>
#include <math.h>

#define T_LEN    8192
#define NDELAY   360
#define NTHREADS 1024
#define FULLMASK 0xffffffffu

// smem float layout: [FPX zeros | X 8192 | 2048 tail] [FPB zeros | B 8192 | 2048 tail]
#define FPX 424     // >= L1+1 (max 421)
#define FPB 848     // >= 2*L1+2 (max 842); also serial-Y front pad (>=4)
#define TAILP 2048  // serial 2-slot stray reach
#define OX  0
#define OB  (OX + FPX + T_LEN + TAILP)
#define SMEM_FLOATS (OB + FPB + T_LEN + TAILP)

// ---------------------------------------------------------------------------
// y_t = x_t - a1*y_{t-L1} - a2*y_{t-L2}; exactly two taps (straight-through
// one-hot exactly hard in fp32). L2 = L1+1 unless m==359 (fallback kept).
// K=2 squaring for ALL L1:  y = x(1-s)(1+s^2)/(1-s^4),  W = 4*L1 in [516,1680].
//   pass1: B = (1-s)X       pass2: X = (1+s^2)B   (register-carried centers)
//   serial: y = w2 + s^4 y, taps at consecutive lags W..W+4.
// Serial engine, contiguous-pair layout: thread p owns slots 2p, 2p+1.
//   tap slot 2p-k / 2p+1-k -> shfl_up of reg (k+1)/2 or own reg; the two
//   slots SHARE taps, so 4 shfls + 2 register reads serve all 10 tap reads.
//   Boundary lanes (lane<dist) read the Y smem image of the previous round
//   (front-pad zeros for t<0). Only ceil(W/64) warps execute the round body.
// Stray slots (2p>=W) write only into LATER rounds' regions (smem+gmem) and
// are overwritten before any read -- __syncthreads orders both spaces.
// ---------------------------------------------------------------------------

__device__ __forceinline__ float tanh_fast(float x) {
    x = fminf(fmaxf(x, -15.0f), 15.0f);
    float e = __expf(2.0f * x);
    return (e - 1.0f) * __frcp_rn(e + 1.0f);
}

__global__ void __launch_bounds__(NTHREADS, 1)
ks_fused_kernel(const float* __restrict__ x,
                const float* __restrict__ gumbel,
                const float* __restrict__ delayp,
                const float* __restrict__ fb,
                const float* __restrict__ rc,
                float* __restrict__ out) {
    extern __shared__ float sm[];
    float* Xd = sm + OX + FPX;
    float* Bd = sm + OB + FPB;

    __shared__ float s_rv[32];
    __shared__ int   s_ri[32];
    __shared__ int   s_m;
    __shared__ float s_a1, s_a2;

    const int tid  = threadIdx.x;
    const int row  = blockIdx.x;
    const int lane = tid & 31;
    const int wid  = tid >> 5;
    const float* xr = x + (size_t)row * T_LEN;
    float*       yr = out + (size_t)row * T_LEN;

    // --- stage x (coalesced float4; LDG latency hidden under setup) ---
    {
        const float4* x4 = (const float4*)xr;
        float4* s4 = (float4*)Xd;
        s4[tid]            = x4[tid];
        s4[tid + NTHREADS] = x4[tid + NTHREADS];
    }

    // --- zero front pads ---
    if (tid < FPX) sm[OX + tid] = 0.0f;
    if (tid < FPB) sm[OB + tid] = 0.0f;

    // --- thread 0: scalar coefficients (once; uses the argmax barrier) ---
    if (tid == 0) {
        float k1 = tanh_fast(tanh_fast(rc[0]));
        float k2 = tanh_fast(tanh_fast(rc[1]));
        float a1 = k1 * (1.0f - k2);
        float a2 = fminf(fmaxf(k2, -0.999f), 0.999f);
        float bound = 0.999f - fabsf(a2);
        a1 = fminf(fmaxf(a1, -bound), bound);
        float sg = __frcp_rn(1.0f + __expf(-fb[0]));
        float g  = __powf(sg, 0.45f);
        s_a1 = a1 * g;
        s_a2 = a2 * g;
    }

    // --- argmax over 360 logits (first-index tie-break) ---
    float lv = -INFINITY;
    int   li = tid;
    if (tid < NDELAY) lv = delayp[tid] + gumbel[tid];
#pragma unroll
    for (int off = 16; off > 0; off >>= 1) {
        float ov = __shfl_down_sync(FULLMASK, lv, off);
        int   oi = __shfl_down_sync(FULLMASK, li, off);
        if (ov > lv || (ov == lv && oi < li)) { lv = ov; li = oi; }
    }
    if (lane == 0) { s_rv[wid] = lv; s_ri[wid] = li; }
    __syncthreads();
    if (tid < 32) {
        lv = s_rv[lane];
        li = s_ri[lane];
#pragma unroll
        for (int off = 16; off > 0; off >>= 1) {
            float ov = __shfl_down_sync(FULLMASK, lv, off);
            int   oi = __shfl_down_sync(FULLMASK, li, off);
            if (ov > lv || (ov == lv && oi < li)) { lv = ov; li = oi; }
        }
        if (lane == 0) s_m = li;
    }
    __syncthreads();   // staging + pads + argmax + coeffs complete

    const int   m  = s_m;
    const int   L1 = 61 + m;
    const int   L2 = 61 + ((m + 1) % NDELAY);
    const float a1 = s_a1;
    const float a2 = s_a2;

    if (L2 != L1 + 1) {
        // --- fallback (m == 359 only): in-place barrier rounds, width C ---
        const int C = (L1 < L2) ? L1 : L2;
        for (int t = tid; t < C; t += NTHREADS) yr[t] = Xd[t];
        for (int s0 = C; s0 < T_LEN; s0 += C) {
            __syncthreads();
            const int t = s0 + tid;
            if (tid < C && t < T_LEN) {
                float y = Xd[t] - a1 * Xd[t - L1] - a2 * Xd[t - L2];
                Xd[t] = y;
                yr[t] = y;
            }
        }
        return;
    }

    const float a1_2 = a1 * a1, a2_2 = a2 * a2;

    // --- pass 1: B = (1 - s) X, register carry (lags L1, L1+1) ---
    float rc8[8];
#pragma unroll
    for (int i = 0; i < 8; i++) {
        const int t = i * NTHREADS + tid;
        float w = fmaf(-a1, Xd[t - L1], Xd[t]);
        w = fmaf(-a2, Xd[t - L1 - 1], w);
        Bd[t] = w;
        rc8[i] = w;
    }
    __syncthreads();

    // --- pass 2: X = (1 + s^2) B  (lags 2L1..2L1+2) ---
    {
        const float q0 = a1_2, q1 = 2.0f * a1 * a2, q2 = a2_2;
        const int gl = 2 * L1;
#pragma unroll
        for (int i = 0; i < 8; i++) {
            const int t = i * NTHREADS + tid;
            float w = fmaf(q0, Bd[t - gl], rc8[i]);
            w = fmaf(q1, Bd[t - gl - 1], w);
            w = fmaf(q2, Bd[t - gl - 2], w);
            Xd[t] = w;
        }
    }
    __syncthreads();

    // --- serial: y = w2 + s^4 y, taps at W..W+4, W = 4*L1 ---
    {
        const float c0 = a1_2 * a1_2;
        const float c1 = 4.0f * a1_2 * a1 * a2;
        const float c2 = 6.0f * a1_2 * a2_2;
        const float c3 = 4.0f * a1 * a2_2 * a2;
        const float c4 = a2_2 * a2_2;
        const int   W  = 4 * L1;
        const int   p2 = 2 * tid;
        float* Y = Bd;                       // B is dead; reuse as serial image
        const bool wact = (64 * wid < W);    // warp has at least one valid slot

        // round 0: y = w2 on [0, W) (strays overwritten later)
        float y0 = Xd[p2], y1 = Xd[p2 + 1];
        if (wact) {
            Y[p2] = y0;  Y[p2 + 1] = y1;
            yr[p2] = y0; yr[p2 + 1] = y1;
        }
        __syncthreads();

        for (int s0 = W; s0 < T_LEN; s0 += W) {
            if (wact) {
                const int t0 = s0 + p2;
                float cx0 = Xd[t0], cx1 = Xd[t0 + 1];
                // shared taps: shfl_up of both regs at distances 1 and 2
                float a01 = __shfl_up_sync(FULLMASK, y0, 1);
                float a02 = __shfl_up_sync(FULLMASK, y0, 2);
                float a11 = __shfl_up_sync(FULLMASK, y1, 1);
                float a12 = __shfl_up_sync(FULLMASK, y1, 2);
                const int q0 = t0 - W;       // prev-round index of slot 2p
                float t01 = (lane < 1) ? Y[q0 - 1] : a11;  // slot 2p-1
                float t02 = (lane < 1) ? Y[q0 - 2] : a01;  // slot 2p-2
                float t03 = (lane < 2) ? Y[q0 - 3] : a12;  // slot 2p-3
                float t04 = (lane < 2) ? Y[q0 - 4] : a02;  // slot 2p-4
                // slot 2p:   taps k=1..4 -> t01..t04 ; k=0 -> y0
                float n0 = fmaf(c0, y0, cx0);
                n0 = fmaf(c1, t01, n0);
                n0 = fmaf(c2, t02, n0);
                n0 = fmaf(c3, t03, n0);
                n0 = fmaf(c4, t04, n0);
                // slot 2p+1: k=0 -> y1; k=1 -> y0; k=2..4 -> t01..t03
                float n1 = fmaf(c0, y1, cx1);
                n1 = fmaf(c1, y0, n1);
                n1 = fmaf(c2, t01, n1);
                n1 = fmaf(c3, t02, n1);
                n1 = fmaf(c4, t03, n1);
                Y[t0] = n0;  Y[t0 + 1] = n1;
                if (t0 < T_LEN)     yr[t0] = n0;
                if (t0 + 1 < T_LEN) yr[t0 + 1] = n1;
                y0 = n0; y1 = n1;
            }
            __syncthreads();
        }
    }
}

// ---------------------------------------------------------------------------
// inputs: excitation[128*8192] f32, gumbel[360], delay_param[360],
//         feedback_gain[1], reflection_coeffs[2]; output f32 [128*8192]
// ---------------------------------------------------------------------------
extern "C" void kernel_launch(void* const* d_in, const int* in_sizes, int n_in,
                              void* d_out, int out_size) {
    const float* x      = (const float*)d_in[0];
    const float* gumbel = (const float*)d_in[1];
    const float* delayp = (const float*)d_in[2];
    const float* fb     = (const float*)d_in[3];
    const float* rc     = (const float*)d_in[4];
    float* out = (float*)d_out;

    const int rows = in_sizes[0] / T_LEN;
    const int smem_bytes = SMEM_FLOATS * sizeof(float);

    cudaFuncSetAttribute(ks_fused_kernel,
                         cudaFuncAttributeMaxDynamicSharedMemorySize, smem_bytes);
    ks_fused_kernel<<<rows, NTHREADS, smem_bytes>>>(x, gumbel, delayp, fb, rc, out);
}

// round 16
// speedup vs baseline: 1.1176x; 1.0948x over previous
#include <cuda_runtime.h>
#include <math.h>

#define T_LEN    8192
#define NDELAY   360
#define NTHREADS 512
#define PAD      424              // >= max lag 420, so no tap guards
#define FULLMASK 0xffffffffu

// ---------------------------------------------------------------------------
// y_t = x_t - a1*y_{t-L1} - a2*y_{t-L2}; exactly two taps (the straight-
// through Gumbel one-hot is exactly hard in fp32: (0-s)+s == 0 for the zero
// entries), L1 = 61+m, L2 = 61+((m+1)%360), both >= 61.
// Samples within a window of C = min(L1,L2) are independent, so the scan
// parallelizes into ceil(8192/C) barrier-separated rounds (R1's engine —
// empirically the fastest structure measured across 15 rounds).
// This version fuses the setup (argmax + coeffs) into the kernel under the
// staging-load latency, and dual-stores (STS+STG) inside the rounds so the
// final writeback pass disappears. One code path for every m (incl. 359).
// ---------------------------------------------------------------------------

__device__ __forceinline__ float tanh_fast(float x) {
    x = fminf(fmaxf(x, -15.0f), 15.0f);
    float e = __expf(2.0f * x);
    return (e - 1.0f) * __frcp_rn(e + 1.0f);
}

__global__ void __launch_bounds__(NTHREADS)
ks_fused_kernel(const float* __restrict__ x,
                const float* __restrict__ gumbel,
                const float* __restrict__ delayp,
                const float* __restrict__ fb,
                const float* __restrict__ rc,
                float* __restrict__ out) {
    __shared__ float buf[PAD + T_LEN];    // static smem: pad zeros + row
    __shared__ float s_rv[16];
    __shared__ int   s_ri[16];
    __shared__ int   s_m;

    float* A = buf + PAD;

    const int tid  = threadIdx.x;
    const int row  = blockIdx.x;
    const int lane = tid & 31;
    const int wid  = tid >> 5;
    const float* xr = x + (size_t)row * T_LEN;
    float*       yr = out + (size_t)row * T_LEN;

    // --- stage x (coalesced float4); setup below hides the LDG latency ---
    {
        const float4* x4 = (const float4*)xr;
        float4* a4 = (float4*)A;
#pragma unroll
        for (int i = 0; i < T_LEN / 4 / NTHREADS; i++)
            a4[tid + i * NTHREADS] = x4[tid + i * NTHREADS];
        if (tid < PAD) buf[tid] = 0.0f;
    }

    // --- argmax over 360 logits (first-index tie-break) ---
    float lv = -INFINITY;
    int   li = tid;
    if (tid < NDELAY) lv = delayp[tid] + gumbel[tid];
#pragma unroll
    for (int off = 16; off > 0; off >>= 1) {
        float ov = __shfl_down_sync(FULLMASK, lv, off);
        int   oi = __shfl_down_sync(FULLMASK, li, off);
        if (ov > lv || (ov == lv && oi < li)) { lv = ov; li = oi; }
    }
    if (lane == 0) { s_rv[wid] = lv; s_ri[wid] = li; }

    // --- scalar coefficients (redundant per thread; fast intrinsics) ---
    float k1 = tanh_fast(tanh_fast(rc[0]));
    float k2 = tanh_fast(tanh_fast(rc[1]));
    float a1 = k1 * (1.0f - k2);
    float a2 = fminf(fmaxf(k2, -0.999f), 0.999f);
    float bound = 0.999f - fabsf(a2);
    a1 = fminf(fmaxf(a1, -bound), bound);
    float sg = __frcp_rn(1.0f + __expf(-fb[0]));
    float g  = __powf(sg, 0.45f);
    a1 *= g;
    a2 *= g;

    __syncthreads();
    if (tid < 32) {
        lv = (lane < 16) ? s_rv[lane] : -INFINITY;
        li = (lane < 16) ? s_ri[lane] : 0x7fffffff;
#pragma unroll
        for (int off = 8; off > 0; off >>= 1) {
            float ov = __shfl_down_sync(FULLMASK, lv, off);
            int   oi = __shfl_down_sync(FULLMASK, li, off);
            if (ov > lv || (ov == lv && oi < li)) { lv = ov; li = oi; }
        }
        if (lane == 0) s_m = li;
    }
    __syncthreads();   // staging + pad + argmax complete

    const int m  = s_m;
    const int L1 = 61 + m;
    const int L2 = 61 + ((m + 1) % NDELAY);
    const int C  = (L1 < L2) ? L1 : L2;

    // --- serial rounds, width C, in place; dual store STS + STG ---
    // Round 0 reads only pad zeros (lags >= C >= 61 <= PAD), so one uniform
    // loop covers everything. Taps always hit earlier rounds (lags >= C),
    // which the barrier ordered. Single-compare store/compute guard.
    for (int s0 = 0; s0 < T_LEN; s0 += C) {
        const int t   = s0 + tid;
        const int lim = (s0 + C < T_LEN) ? (s0 + C) : T_LEN;
        if (t < lim) {
            float y = fmaf(-a2, A[t - L2], fmaf(-a1, A[t - L1], A[t]));
            A[t]  = y;
            yr[t] = y;
        }
        __syncthreads();
    }
}

// ---------------------------------------------------------------------------
// inputs: excitation[128*8192] f32, gumbel[360], delay_param[360],
//         feedback_gain[1], reflection_coeffs[2]; output f32 [128*8192]
// ---------------------------------------------------------------------------
extern "C" void kernel_launch(void* const* d_in, const int* in_sizes, int n_in,
                              void* d_out, int out_size) {
    const float* x      = (const float*)d_in[0];
    const float* gumbel = (const float*)d_in[1];
    const float* delayp = (const float*)d_in[2];
    const float* fb     = (const float*)d_in[3];
    const float* rc     = (const float*)d_in[4];
    float* out = (float*)d_out;

    const int rows = in_sizes[0] / T_LEN;
    ks_fused_kernel<<<rows, NTHREADS>>>(x, gumbel, delayp, fb, rc, out);
}